// round 4
// baseline (speedup 1.0000x reference)
#include <cuda_runtime.h>
#include <cstdint>

// LinearBlendSkinning: out[n] = (sum_j w[n,j]*SE3[j])[:3,:3] @ p[n] + (...)[:3,3]
// N = 1e6 verts, J = 55 joints.
//
// Strategy:
//  - Block tile of BV=192 vertices. Weights tile is CONTIGUOUS in global
//    (row-major [N,55]) -> stage to SMEM via coalesced float4 memcpy.
//  - SE3 rows 0..2 staged once per block as 16B-aligned ulonglong2 (float4).
//  - Each thread accumulates V=2 vertices; per joint: 2 weight LDS.32
//    (word-stride 55, odd -> conflict-free), 3 LDS.128 SE3 broadcasts shared
//    across both vertices, 12 packed fma.rn.f32x2 (FFMA2) into f32x2 pairs.
//  - Epilogue: unpack A rows, 3x (dot3 + T), scalar stores.

#define NJ   55
#define BT   96          // threads per block (3 warps)
#define VPT  2           // vertices per thread
#define BV   (BT * VPT)  // 192 vertices per block

#define FMA2(acc, s, m) \
    asm("fma.rn.f32x2 %0, %1, %2, %0;" : "+l"(acc) : "l"(s), "l"(m))

#define PACK_DUP(dst, f) \
    asm("mov.b64 %0, {%1, %1};" : "=l"(dst) : "f"(f))

#define UNPACK2(lo, hi, src) \
    asm("mov.b64 {%0, %1}, %2;" : "=f"(lo), "=f"(hi) : "l"(src))

__global__ void __launch_bounds__(BT) lbs_kernel(
    const float* __restrict__ points,   // [N,3]
    const float* __restrict__ weights,  // [N,55]
    const float* __restrict__ se3,      // [55,4,4]
    float* __restrict__ out,            // [N,3]
    int N)
{
    __shared__ float      w_s[BV * NJ];       // 42240 B
    __shared__ ulonglong2 se3_s[NJ * 3];      //  2640 B  (rows 0..2, 16B each)

    const int tid   = threadIdx.x;
    const int vbase = blockIdx.x * BV;
    const int nv    = min(BV, N - vbase);

    // ---- stage SE3 rows 0..2: each row = one aligned 16B load ----
    for (int idx = tid; idx < NJ * 3; idx += BT) {
        const int j = idx / 3, k = idx - j * 3;
        se3_s[idx] = *reinterpret_cast<const ulonglong2*>(se3 + j * 16 + k * 4);
    }

    // ---- stage weights tile: straight contiguous copy (coalesced) ----
    {
        const long long base = (long long)vbase * NJ;
        const int nflt = nv * NJ;
        const int n4   = nflt >> 2;
        const float4* src = reinterpret_cast<const float4*>(weights + base);
        float4*       dst = reinterpret_cast<float4*>(w_s);
        for (int i = tid; i < n4; i += BT) dst[i] = src[i];
        for (int i = (n4 << 2) + tid; i < nflt; i += BT)
            w_s[i] = weights[base + i];
    }
    __syncthreads();

    // ---- per-thread: 2 vertices ----
    const int l0 = tid, l1 = tid + BT;
    const bool valid0 = (l0 < nv), valid1 = (l1 < nv);
    const int v0 = vbase + l0, v1 = vbase + l1;
    const int pv0 = valid0 ? v0 : 0;
    const int pv1 = valid1 ? v1 : 0;

    const float p0x = points[3 * pv0 + 0];
    const float p0y = points[3 * pv0 + 1];
    const float p0z = points[3 * pv0 + 2];
    const float p1x = points[3 * pv1 + 0];
    const float p1y = points[3 * pv1 + 1];
    const float p1z = points[3 * pv1 + 2];

    // Accumulators: A row k = 4 floats = 2 f32x2 pairs. Per vertex 6 pairs.
    unsigned long long a000 = 0, a001 = 0, a010 = 0, a011 = 0, a020 = 0, a021 = 0;
    unsigned long long a100 = 0, a101 = 0, a110 = 0, a111 = 0, a120 = 0, a121 = 0;

    const float* __restrict__ w0p = w_s + l0 * NJ;
    const float* __restrict__ w1p = w_s + l1 * NJ;

    #pragma unroll 11
    for (int j = 0; j < NJ; j++) {
        const float w0 = w0p[j];
        const float w1 = w1p[j];
        unsigned long long ww0, ww1;
        PACK_DUP(ww0, w0);
        PACK_DUP(ww1, w1);

        const ulonglong2 r0 = se3_s[j * 3 + 0];
        const ulonglong2 r1 = se3_s[j * 3 + 1];
        const ulonglong2 r2 = se3_s[j * 3 + 2];

        FMA2(a000, ww0, r0.x); FMA2(a001, ww0, r0.y);
        FMA2(a010, ww0, r1.x); FMA2(a011, ww0, r1.y);
        FMA2(a020, ww0, r2.x); FMA2(a021, ww0, r2.y);

        FMA2(a100, ww1, r0.x); FMA2(a101, ww1, r0.y);
        FMA2(a110, ww1, r1.x); FMA2(a111, ww1, r1.y);
        FMA2(a120, ww1, r2.x); FMA2(a121, ww1, r2.y);
    }

    // ---- epilogue: out = R*p + T ----
    float m0, m1, m2, m3;
    if (valid0) {
        float o[3];
        UNPACK2(m0, m1, a000); UNPACK2(m2, m3, a001);
        o[0] = fmaf(m0, p0x, fmaf(m1, p0y, fmaf(m2, p0z, m3)));
        UNPACK2(m0, m1, a010); UNPACK2(m2, m3, a011);
        o[1] = fmaf(m0, p0x, fmaf(m1, p0y, fmaf(m2, p0z, m3)));
        UNPACK2(m0, m1, a020); UNPACK2(m2, m3, a021);
        o[2] = fmaf(m0, p0x, fmaf(m1, p0y, fmaf(m2, p0z, m3)));
        out[3 * v0 + 0] = o[0];
        out[3 * v0 + 1] = o[1];
        out[3 * v0 + 2] = o[2];
    }
    if (valid1) {
        float o[3];
        UNPACK2(m0, m1, a100); UNPACK2(m2, m3, a101);
        o[0] = fmaf(m0, p1x, fmaf(m1, p1y, fmaf(m2, p1z, m3)));
        UNPACK2(m0, m1, a110); UNPACK2(m2, m3, a111);
        o[1] = fmaf(m0, p1x, fmaf(m1, p1y, fmaf(m2, p1z, m3)));
        UNPACK2(m0, m1, a120); UNPACK2(m2, m3, a121);
        o[2] = fmaf(m0, p1x, fmaf(m1, p1y, fmaf(m2, p1z, m3)));
        out[3 * v1 + 0] = o[0];
        out[3 * v1 + 1] = o[1];
        out[3 * v1 + 2] = o[2];
    }
}

extern "C" void kernel_launch(void* const* d_in, const int* in_sizes, int n_in,
                              void* d_out, int out_size)
{
    const float* points  = (const float*)d_in[0];  // [N,3]
    const float* weights = (const float*)d_in[1];  // [N,55]
    const float* se3     = (const float*)d_in[2];  // [55,4,4]
    float* out           = (float*)d_out;          // [N,3]

    const int N = in_sizes[0] / 3;
    const int grid = (N + BV - 1) / BV;
    lbs_kernel<<<grid, BT>>>(points, weights, se3, out, N);
}